// round 1
// baseline (speedup 1.0000x reference)
#include <cuda_runtime.h>

#define NN 32
#define PP 256   // H*W
#define FF 256
#define BB 64
#define CC 8
#define BC 512   // B*C
#define KCHUNK 16

// smem layout (floats):
//   xs[32][256]      = 8192
//   Ts[16][512]      = 8192
//   Ms[32][512]      = 16384
// total 32768 floats = 131072 bytes
#define SMEM_FLOATS (NN*FF + KCHUNK*BC + NN*BC)

__global__ __launch_bounds__(256, 1)
void mbd_kernel(const float* __restrict__ x, const float* __restrict__ T,
                float* __restrict__ out) {
    extern __shared__ float smem[];
    float* xs = smem;                      // [32][256]
    float* Ts = smem + NN*FF;              // [16][512]
    float* Ms = smem + NN*FF + KCHUNK*BC;  // [32][512]

    const int p = blockIdx.x;
    const int t = threadIdx.x;

    // ---- Phase 1: load x tile for this pixel + passthrough to out channels [0,256) ----
    // 8192 floats = 2048 float4; each thread moves 8 float4.
    #pragma unroll
    for (int it = 0; it < 8; ++it) {
        int idx4 = t + 256 * it;          // 0..2047
        int n    = idx4 >> 6;             // 64 float4 per n-row
        int f4   = idx4 & 63;
        float4 v = *reinterpret_cast<const float4*>(
            x + ((size_t)(n * PP + p)) * FF + f4 * 4);
        reinterpret_cast<float4*>(xs)[idx4] = v;
        *reinterpret_cast<float4*>(
            out + ((size_t)(n * PP + p)) * (FF + BB) + f4 * 4) = v;
    }
    __syncthreads();

    // ---- Phase 2: GEMM  Ms[n][col] = sum_k xs[n][k] * T[k][col] ----
    // thread tile: 4 n-rows x 16 cols (cols interleaved by 32 for conflict-free LDS)
    const int cg = t & 31;    // column group 0..31
    const int ng = t >> 5;    // n group 0..7 (whole warp shares ng -> xs broadcast)
    float acc[4][16];
    #pragma unroll
    for (int i = 0; i < 4; ++i)
        #pragma unroll
        for (int j = 0; j < 16; ++j) acc[i][j] = 0.f;

    for (int ko = 0; ko < FF / KCHUNK; ++ko) {
        // stage T chunk [16][512] = 2048 float4
        #pragma unroll
        for (int it = 0; it < 8; ++it) {
            int idx4 = t + 256 * it;
            reinterpret_cast<float4*>(Ts)[idx4] =
                *reinterpret_cast<const float4*>(
                    T + (size_t)ko * KCHUNK * BC + (size_t)idx4 * 4);
        }
        __syncthreads();
        #pragma unroll
        for (int kk = 0; kk < KCHUNK; ++kk) {
            float xv[4];
            #pragma unroll
            for (int i = 0; i < 4; ++i)
                xv[i] = xs[(ng * 4 + i) * FF + ko * KCHUNK + kk];
            #pragma unroll
            for (int j = 0; j < 16; ++j) {
                float tv = Ts[kk * BC + cg + 32 * j];
                #pragma unroll
                for (int i = 0; i < 4; ++i)
                    acc[i][j] = fmaf(xv[i], tv, acc[i][j]);
            }
        }
        __syncthreads();
    }
    // write M tile to smem
    #pragma unroll
    for (int i = 0; i < 4; ++i)
        #pragma unroll
        for (int j = 0; j < 16; ++j)
            Ms[(ng * 4 + i) * BC + cg + 32 * j] = acc[i][j];
    __syncthreads();

    // ---- Phase 3: pairwise L1 + exp ----
    // thread owns b = t&63, 8 n-rows (ng2*8 + i)
    const int b   = t & 63;
    const int ng2 = t >> 6;   // 0..3
    float m[8][8];
    #pragma unroll
    for (int i = 0; i < 8; ++i) {
        const float* row = &Ms[(ng2 * 8 + i) * BC + b * CC];
        float4 v0 = *reinterpret_cast<const float4*>(row);
        float4 v1 = *reinterpret_cast<const float4*>(row + 4);
        m[i][0] = v0.x; m[i][1] = v0.y; m[i][2] = v0.z; m[i][3] = v0.w;
        m[i][4] = v1.x; m[i][5] = v1.y; m[i][6] = v1.z; m[i][7] = v1.w;
    }
    float o[8];
    #pragma unroll
    for (int i = 0; i < 8; ++i) o[i] = 0.f;

    #pragma unroll 4
    for (int j = 0; j < NN; ++j) {
        const float* row = &Ms[j * BC + b * CC];
        float4 v0 = *reinterpret_cast<const float4*>(row);
        float4 v1 = *reinterpret_cast<const float4*>(row + 4);
        float mj[8] = {v0.x, v0.y, v0.z, v0.w, v1.x, v1.y, v1.z, v1.w};
        #pragma unroll
        for (int i = 0; i < 8; ++i) {
            float s = 0.f;
            #pragma unroll
            for (int c = 0; c < 8; ++c) s += fabsf(m[i][c] - mj[c]);
            o[i] += __expf(-s);
        }
    }

    #pragma unroll
    for (int i = 0; i < 8; ++i) {
        int n = ng2 * 8 + i;
        out[((size_t)(n * PP + p)) * (FF + BB) + FF + b] = o[i];
    }
}

extern "C" void kernel_launch(void* const* d_in, const int* in_sizes, int n_in,
                              void* d_out, int out_size) {
    // metadata order: x [32,16,16,256] (2097152), T [256,64,8] (131072).
    // Defensive: identify by size.
    const float* x;
    const float* T;
    if (in_sizes[0] == NN * PP * FF) {
        x = (const float*)d_in[0];
        T = (const float*)d_in[1];
    } else {
        x = (const float*)d_in[1];
        T = (const float*)d_in[0];
    }
    float* out = (float*)d_out;

    cudaFuncSetAttribute(mbd_kernel,
                         cudaFuncAttributeMaxDynamicSharedMemorySize,
                         SMEM_FLOATS * (int)sizeof(float));
    mbd_kernel<<<PP, 256, SMEM_FLOATS * sizeof(float)>>>(x, T, out);
}

// round 3
// speedup vs baseline: 1.9452x; 1.9452x over previous
#include <cuda_runtime.h>
#include <cuda_bf16.h>
#include <cstdint>

#define NN 32
#define PP 256
#define FF 256
#define BB 64
#define BC 512
#define OUTC 320

// ---------------- device scratch ----------------
__device__ __nv_bfloat16 g_Tb_hi[BC * FF];        // [n=512][k=256]
__device__ __nv_bfloat16 g_Tb_lo[BC * FF];
__device__ __nv_bfloat16 g_Xb_hi[NN * PP * FF];   // [r=8192][k=256]
__device__ __nv_bfloat16 g_Xb_lo[NN * PP * FF];
__device__ float g_M[PP * NN * BC];               // [p][n][512]

// ---------------- helpers ----------------
__device__ __forceinline__ uint32_t smem_u32(const void* p) {
    uint32_t a;
    asm("{ .reg .u64 t; cvta.to.shared.u64 t, %1; cvt.u32.u64 %0, t; }"
        : "=r"(a) : "l"(p));
    return a;
}

#define LDSM4(r, addr) \
    asm volatile("ldmatrix.sync.aligned.m8n8.x4.shared.b16 {%0,%1,%2,%3}, [%4];" \
        : "=r"((r)[0]), "=r"((r)[1]), "=r"((r)[2]), "=r"((r)[3]) : "r"(addr))

#define MMA16816(c, a, b0, b1) \
    asm volatile("mma.sync.aligned.m16n8k16.row.col.f32.bf16.bf16.f32 " \
        "{%0,%1,%2,%3}, {%4,%5,%6,%7}, {%8,%9}, {%0,%1,%2,%3};" \
        : "+f"((c)[0]), "+f"((c)[1]), "+f"((c)[2]), "+f"((c)[3]) \
        : "r"((a)[0]), "r"((a)[1]), "r"((a)[2]), "r"((a)[3]), "r"(b0), "r"(b1))

__device__ __forceinline__ unsigned long long fma2(unsigned long long a,
                                                   unsigned long long b,
                                                   unsigned long long c) {
    unsigned long long d;
    asm("fma.rn.f32x2 %0, %1, %2, %3;" : "=l"(d) : "l"(a), "l"(b), "l"(c));
    return d;
}
__device__ __forceinline__ unsigned long long add2(unsigned long long a,
                                                   unsigned long long b) {
    unsigned long long d;
    asm("add.rn.f32x2 %0, %1, %2;" : "=l"(d) : "l"(a), "l"(b));
    return d;
}

// =============== prep 1: transpose + split T ===============
__global__ void mbd_prep_t(const float* __restrict__ T) {
    __shared__ float tile[32][33];
    const int f0 = blockIdx.x * 32;
    const int n0 = blockIdx.y * 32;
    const int tx = threadIdx.x & 31;
    const int ty = threadIdx.x >> 5;
    #pragma unroll
    for (int r = 0; r < 4; ++r)
        tile[ty + 8 * r][tx] = T[(size_t)(f0 + ty + 8 * r) * BC + n0 + tx];
    __syncthreads();
    #pragma unroll
    for (int r = 0; r < 4; ++r) {
        int n = n0 + ty + 8 * r;
        int f = f0 + tx;
        float v = tile[tx][ty + 8 * r];
        __nv_bfloat16 h = __float2bfloat16(v);
        g_Tb_hi[(size_t)n * FF + f] = h;
        g_Tb_lo[(size_t)n * FF + f] = __float2bfloat16(v - __bfloat162float(h));
    }
}

// =============== prep 2: split x + passthrough ===============
__global__ __launch_bounds__(256)
void mbd_prep_x(const float* __restrict__ x, float* __restrict__ out) {
    const int idx4 = blockIdx.x * 256 + threadIdx.x;   // 0..524287 (float4)
    const int r = idx4 >> 6;
    const int u = idx4 & 63;
    float4 v = *reinterpret_cast<const float4*>(x + (size_t)idx4 * 4);
    *reinterpret_cast<float4*>(out + (size_t)r * OUTC + u * 4) = v;
    __nv_bfloat16 h0 = __float2bfloat16(v.x), h1 = __float2bfloat16(v.y);
    __nv_bfloat16 h2 = __float2bfloat16(v.z), h3 = __float2bfloat16(v.w);
    __nv_bfloat162 hi0(h0, h1), hi1(h2, h3);
    __nv_bfloat162 lo0(__float2bfloat16(v.x - __bfloat162float(h0)),
                       __float2bfloat16(v.y - __bfloat162float(h1)));
    __nv_bfloat162 lo1(__float2bfloat16(v.z - __bfloat162float(h2)),
                       __float2bfloat16(v.w - __bfloat162float(h3)));
    *reinterpret_cast<uint2*>(g_Xb_hi + (size_t)idx4 * 4) =
        make_uint2(*reinterpret_cast<uint32_t*>(&hi0),
                   *reinterpret_cast<uint32_t*>(&hi1));
    *reinterpret_cast<uint2*>(g_Xb_lo + (size_t)idx4 * 4) =
        make_uint2(*reinterpret_cast<uint32_t*>(&lo0),
                   *reinterpret_cast<uint32_t*>(&lo1));
}

// =============== GEMM: HMMA, block tile 128x64, K=256 ===============
#define PAD 72                         // padded k-stride (elems) per smem row
#define A_ELEMS (128 * PAD)
#define B_ELEMS (64 * PAD)
#define SMEM_GEMM ((2 * A_ELEMS + 2 * B_ELEMS) * 2)   // 55296 bytes

__global__ __launch_bounds__(128)
void mbd_gemm(float* __restrict__ dummy) {
    extern __shared__ __nv_bfloat16 sm[];
    __nv_bfloat16* Ah = sm;
    __nv_bfloat16* Al = Ah + A_ELEMS;
    __nv_bfloat16* Bh = Al + A_ELEMS;
    __nv_bfloat16* Bl = Bh + B_ELEMS;

    const int t = threadIdx.x, w = t >> 5, lane = t & 31;
    const int bx = blockIdx.x;         // row tile (64)
    const int by = blockIdx.y;         // col tile (8)
    const int mo = (w >> 1) * 64;
    const int no = (w & 1) * 32;

    const uint32_t ah_b = smem_u32(Ah);
    const uint32_t bh_b = smem_u32(Bh);

    float acc[4][4][4];
    #pragma unroll
    for (int i = 0; i < 4; ++i)
        #pragma unroll
        for (int j = 0; j < 4; ++j)
            #pragma unroll
            for (int e = 0; e < 4; ++e) acc[i][j][e] = 0.f;

    for (int kc = 0; kc < 4; ++kc) {
        // stage A: 128 rows x 64 k (hi+lo)
        #pragma unroll
        for (int it = 0; it < 8; ++it) {
            int idx = t + 128 * it;            // uint4 units, 1024 total
            int row = idx >> 3, u = idx & 7;
            size_t src = ((size_t)(bx * 128 + row)) * FF + kc * 64 + u * 8;
            *reinterpret_cast<uint4*>(&Ah[row * PAD + u * 8]) =
                *reinterpret_cast<const uint4*>(&g_Xb_hi[src]);
            *reinterpret_cast<uint4*>(&Al[row * PAD + u * 8]) =
                *reinterpret_cast<const uint4*>(&g_Xb_lo[src]);
        }
        // stage B: 64 rows x 64 k (hi+lo)
        #pragma unroll
        for (int it = 0; it < 4; ++it) {
            int idx = t + 128 * it;            // 512 total
            int row = idx >> 3, u = idx & 7;
            size_t src = ((size_t)(by * 64 + row)) * FF + kc * 64 + u * 8;
            *reinterpret_cast<uint4*>(&Bh[row * PAD + u * 8]) =
                *reinterpret_cast<const uint4*>(&g_Tb_hi[src]);
            *reinterpret_cast<uint4*>(&Bl[row * PAD + u * 8]) =
                *reinterpret_cast<const uint4*>(&g_Tb_lo[src]);
        }
        __syncthreads();

        #pragma unroll
        for (int ks = 0; ks < 4; ++ks) {
            uint32_t afh[4][4], afl[4][4];
            #pragma unroll
            for (int mi = 0; mi < 4; ++mi) {
                uint32_t ad = ah_b +
                    (((mo + mi * 16 + (lane & 15)) * PAD) +
                     ks * 16 + (lane >> 4) * 8) * 2;
                LDSM4(afh[mi], ad);
                LDSM4(afl[mi], ad + A_ELEMS * 2);
            }
            uint32_t bfh[8], bfl[8];
            #pragma unroll
            for (int g = 0; g < 2; ++g) {
                uint32_t bd = bh_b +
                    (((no + g * 16 + ((lane >> 4) & 1) * 8 + (lane & 7)) * PAD) +
                     ks * 16 + ((lane >> 3) & 1) * 8) * 2;
                LDSM4(&bfh[g * 4], bd);
                LDSM4(&bfl[g * 4], bd + B_ELEMS * 2);
            }
            #pragma unroll
            for (int mi = 0; mi < 4; ++mi)
                #pragma unroll
                for (int ni = 0; ni < 4; ++ni) {
                    MMA16816(acc[mi][ni], afh[mi], bfh[ni * 2], bfh[ni * 2 + 1]);
                    MMA16816(acc[mi][ni], afl[mi], bfh[ni * 2], bfh[ni * 2 + 1]);
                    MMA16816(acc[mi][ni], afh[mi], bfl[ni * 2], bfl[ni * 2 + 1]);
                }
        }
        __syncthreads();
    }

    // write out to g_M[p][n][col]
    #pragma unroll
    for (int mi = 0; mi < 4; ++mi)
        #pragma unroll
        for (int ni = 0; ni < 4; ++ni) {
            int gc = by * 64 + no + ni * 8 + (lane & 3) * 2;
            #pragma unroll
            for (int h = 0; h < 2; ++h) {
                int r = bx * 128 + mo + mi * 16 + (lane >> 2) + h * 8;
                int n = r >> 8, p = r & 255;
                *reinterpret_cast<float2*>(&g_M[((size_t)(p * NN + n)) * BC + gc]) =
                    make_float2(acc[mi][ni][h * 2], acc[mi][ni][h * 2 + 1]);
            }
        }
}

// =============== pairwise L1 + exp (f32x2 packed) ===============
__global__ __launch_bounds__(128)
void mbd_pair(float* __restrict__ out) {
    __shared__ float Ms[NN * 128];
    const int p  = blockIdx.x;
    const int bq = blockIdx.y;
    const int t  = threadIdx.x;

    #pragma unroll
    for (int it = 0; it < 8; ++it) {
        int idx4 = t + 128 * it;
        int n = idx4 >> 5, c4 = idx4 & 31;
        reinterpret_cast<float4*>(Ms)[idx4] =
            *reinterpret_cast<const float4*>(
                g_M + ((size_t)p * NN + n) * BC + bq * 128 + c4 * 4);
    }
    __syncthreads();

    const int b  = t & 15;
    const int ig = t >> 4;
    const unsigned long long NEG1 = 0xBF800000BF800000ULL;  // (-1.f, -1.f)
    const unsigned long long AMSK = 0x7FFFFFFF7FFFFFFFULL;

    unsigned long long mi[4][4];
    #pragma unroll
    for (int ii = 0; ii < 4; ++ii) {
        const unsigned long long* row =
            reinterpret_cast<const unsigned long long*>(&Ms[(ig * 4 + ii) * 128 + b * 8]);
        mi[ii][0] = row[0]; mi[ii][1] = row[1];
        mi[ii][2] = row[2]; mi[ii][3] = row[3];
    }
    float o[4] = {0.f, 0.f, 0.f, 0.f};

    #pragma unroll 4
    for (int j = 0; j < NN; ++j) {
        const unsigned long long* row =
            reinterpret_cast<const unsigned long long*>(&Ms[j * 128 + b * 8]);
        unsigned long long jv0 = row[0], jv1 = row[1], jv2 = row[2], jv3 = row[3];
        #pragma unroll
        for (int ii = 0; ii < 4; ++ii) {
            unsigned long long d0 = fma2(jv0, NEG1, mi[ii][0]) & AMSK;
            unsigned long long d1 = fma2(jv1, NEG1, mi[ii][1]) & AMSK;
            unsigned long long d2 = fma2(jv2, NEG1, mi[ii][2]) & AMSK;
            unsigned long long d3 = fma2(jv3, NEG1, mi[ii][3]) & AMSK;
            unsigned long long s2 = add2(add2(d0, d1), add2(d2, d3));
            float s = __uint_as_float((uint32_t)s2) +
                      __uint_as_float((uint32_t)(s2 >> 32));
            o[ii] += __expf(-s);
        }
    }

    #pragma unroll
    for (int ii = 0; ii < 4; ++ii) {
        int n = ig * 4 + ii;
        out[((size_t)(n * PP + p)) * OUTC + FF + bq * 16 + b] = o[ii];
    }
}

// =============== launch ===============
extern "C" void kernel_launch(void* const* d_in, const int* in_sizes, int n_in,
                              void* d_out, int out_size) {
    const float* x;
    const float* T;
    if (in_sizes[0] == NN * PP * FF) {
        x = (const float*)d_in[0];
        T = (const float*)d_in[1];
    } else {
        x = (const float*)d_in[1];
        T = (const float*)d_in[0];
    }
    float* out = (float*)d_out;

    cudaFuncSetAttribute(mbd_gemm,
                         cudaFuncAttributeMaxDynamicSharedMemorySize, SMEM_GEMM);

    mbd_prep_t<<<dim3(8, 16), 256>>>(T);
    mbd_prep_x<<<2048, 256>>>(x, out);
    mbd_gemm<<<dim3(64, 8), 128, SMEM_GEMM>>>(out);
    mbd_pair<<<dim3(PP, 4), 128>>>(out);
}

// round 4
// speedup vs baseline: 2.2249x; 1.1438x over previous
#include <cuda_runtime.h>
#include <cuda_fp16.h>
#include <cstdint>

#define NN 32
#define PP 256
#define FF 256
#define BB 64
#define BC 512
#define OUTC 320

// ---------------- device scratch ----------------
__device__ __half g_Th[BC * FF];          // [n=512][k=256] fp16 (hi only)
__device__ __half g_Xh[NN * PP * FF];     // [r=8192][k=256]
__device__ __half g_Xl[NN * PP * FF];
__device__ float  g_M[PP * NN * BC];      // [p][n][512]

// ---------------- helpers ----------------
__device__ __forceinline__ uint32_t smem_u32(const void* p) {
    uint32_t a;
    asm("{ .reg .u64 t; cvta.to.shared.u64 t, %1; cvt.u32.u64 %0, t; }"
        : "=r"(a) : "l"(p));
    return a;
}

#define LDSM4(r, addr) \
    asm volatile("ldmatrix.sync.aligned.m8n8.x4.shared.b16 {%0,%1,%2,%3}, [%4];" \
        : "=r"((r)[0]), "=r"((r)[1]), "=r"((r)[2]), "=r"((r)[3]) : "r"(addr))

#define MMA_F16(c, a, b0, b1) \
    asm volatile("mma.sync.aligned.m16n8k16.row.col.f32.f16.f16.f32 " \
        "{%0,%1,%2,%3}, {%4,%5,%6,%7}, {%8,%9}, {%0,%1,%2,%3};" \
        : "+f"((c)[0]), "+f"((c)[1]), "+f"((c)[2]), "+f"((c)[3]) \
        : "r"((a)[0]), "r"((a)[1]), "r"((a)[2]), "r"((a)[3]), "r"(b0), "r"(b1))

__device__ __forceinline__ void cp16(uint32_t dst, const void* src) {
    asm volatile("cp.async.cg.shared.global [%0], [%1], 16;"
                 :: "r"(dst), "l"(src) : "memory");
}
#define CP_COMMIT() asm volatile("cp.async.commit_group;" ::: "memory")
#define CP_WAIT(n)  asm volatile("cp.async.wait_group %0;" :: "n"(n) : "memory")

__device__ __forceinline__ unsigned long long fma2(unsigned long long a,
                                                   unsigned long long b,
                                                   unsigned long long c) {
    unsigned long long d;
    asm("fma.rn.f32x2 %0, %1, %2, %3;" : "=l"(d) : "l"(a), "l"(b), "l"(c));
    return d;
}
__device__ __forceinline__ unsigned long long add2(unsigned long long a,
                                                   unsigned long long b) {
    unsigned long long d;
    asm("add.rn.f32x2 %0, %1, %2;" : "=l"(d) : "l"(a), "l"(b));
    return d;
}

// =============== prep 1: transpose T -> fp16 K-major ===============
__global__ void mbd_prep_t(const float* __restrict__ T) {
    __shared__ float tile[32][33];
    const int f0 = blockIdx.x * 32;
    const int n0 = blockIdx.y * 32;
    const int tx = threadIdx.x & 31;
    const int ty = threadIdx.x >> 5;
    #pragma unroll
    for (int r = 0; r < 4; ++r)
        tile[ty + 8 * r][tx] = T[(size_t)(f0 + ty + 8 * r) * BC + n0 + tx];
    __syncthreads();
    #pragma unroll
    for (int r = 0; r < 4; ++r) {
        int n = n0 + ty + 8 * r;
        int f = f0 + tx;
        g_Th[(size_t)n * FF + f] = __float2half(tile[tx][ty + 8 * r]);
    }
}

// =============== prep 2: split x -> fp16 hi/lo + passthrough ===============
__global__ __launch_bounds__(256)
void mbd_prep_x(const float* __restrict__ x, float* __restrict__ out) {
    const int idx4 = blockIdx.x * 256 + threadIdx.x;   // float4 units
    const int r = idx4 >> 6;
    const int u = idx4 & 63;
    float4 v = *reinterpret_cast<const float4*>(x + (size_t)idx4 * 4);
    *reinterpret_cast<float4*>(out + (size_t)r * OUTC + u * 4) = v;
    __half h0 = __float2half(v.x), h1 = __float2half(v.y);
    __half h2 = __float2half(v.z), h3 = __float2half(v.w);
    __half2 hi0(h0, h1), hi1(h2, h3);
    __half2 lo0(__float2half(v.x - __half2float(h0)),
                __float2half(v.y - __half2float(h1)));
    __half2 lo1(__float2half(v.z - __half2float(h2)),
                __float2half(v.w - __half2float(h3)));
    *reinterpret_cast<uint2*>(g_Xh + (size_t)idx4 * 4) =
        make_uint2(*reinterpret_cast<uint32_t*>(&hi0),
                   *reinterpret_cast<uint32_t*>(&hi1));
    *reinterpret_cast<uint2*>(g_Xl + (size_t)idx4 * 4) =
        make_uint2(*reinterpret_cast<uint32_t*>(&lo0),
                   *reinterpret_cast<uint32_t*>(&lo1));
}

// =============== GEMM: fp16 2-split HMMA, tile 128x128, double-buffered ===============
#define PAD 72
#define SA (128 * PAD)                   // halves per array per stage
#define STAGE_HALVES (3 * SA)
#define SMEM_GEMM (2 * STAGE_HALVES * 2) // 110592 bytes

__global__ __launch_bounds__(256, 2)
void mbd_gemm() {
    extern __shared__ __half sm[];
    const uint32_t smb = smem_u32(sm);
    const int t = threadIdx.x, w = t >> 5, lane = t & 31;
    const int bx = blockIdx.x;           // 64 row tiles
    const int by = blockIdx.y;           // 4 col tiles
    const int mo = (w >> 1) * 32;        // warp m offset (0,32,64,96)
    const int no = (w & 1) * 64;         // warp n offset (0,64)

    float acc[2][8][4];
    #pragma unroll
    for (int i = 0; i < 2; ++i)
        #pragma unroll
        for (int j = 0; j < 8; ++j)
            #pragma unroll
            for (int e = 0; e < 4; ++e) acc[i][j][e] = 0.f;

    // staging lambda-ish: issue cp.async for chunk kc into stage s
    auto stage = [&](int kc, int s) {
        const uint32_t base = smb + (uint32_t)(s * STAGE_HALVES) * 2;
        #pragma unroll
        for (int it = 0; it < 4; ++it) {
            int idx = t + 256 * it;          // 0..1023 (16B chunks)
            int row = idx >> 3, u = idx & 7;
            uint32_t doff = (uint32_t)(row * PAD + u * 8) * 2;
            size_t so = (size_t)(bx * 128 + row) * FF + kc * 64 + u * 8;
            cp16(base + doff,            g_Xh + so);
            cp16(base + SA * 2 + doff,   g_Xl + so);
            size_t sb = (size_t)(by * 128 + row) * FF + kc * 64 + u * 8;
            cp16(base + 2 * SA * 2 + doff, g_Th + sb);
        }
        CP_COMMIT();
    };

    stage(0, 0);

    for (int kc = 0; kc < 4; ++kc) {
        if (kc < 3) stage(kc + 1, (kc + 1) & 1);
        if (kc < 3) { CP_WAIT(1); } else { CP_WAIT(0); }
        __syncthreads();

        const int s = kc & 1;
        const uint32_t a_base = smb + (uint32_t)(s * STAGE_HALVES) * 2;
        const uint32_t b_base = a_base + 2 * SA * 2;

        #pragma unroll
        for (int ks = 0; ks < 4; ++ks) {
            uint32_t afh[2][4], afl[2][4];
            #pragma unroll
            for (int mi = 0; mi < 2; ++mi) {
                uint32_t ad = a_base +
                    (uint32_t)(((mo + mi * 16 + (lane & 15)) * PAD) +
                               ks * 16 + (lane >> 4) * 8) * 2;
                LDSM4(afh[mi], ad);
                LDSM4(afl[mi], ad + SA * 2);
            }
            uint32_t bf[16];
            #pragma unroll
            for (int g = 0; g < 4; ++g) {
                uint32_t bd = b_base +
                    (uint32_t)(((no + g * 16 + ((lane >> 4) & 1) * 8 + (lane & 7)) * PAD) +
                               ks * 16 + ((lane >> 3) & 1) * 8) * 2;
                LDSM4(&bf[g * 4], bd);
            }
            #pragma unroll
            for (int mi = 0; mi < 2; ++mi)
                #pragma unroll
                for (int ni = 0; ni < 8; ++ni) {
                    MMA_F16(acc[mi][ni], afh[mi], bf[ni * 2], bf[ni * 2 + 1]);
                    MMA_F16(acc[mi][ni], afl[mi], bf[ni * 2], bf[ni * 2 + 1]);
                }
        }
        __syncthreads();
    }

    // epilogue -> g_M[p][n][col]
    #pragma unroll
    for (int mi = 0; mi < 2; ++mi)
        #pragma unroll
        for (int ni = 0; ni < 8; ++ni) {
            int gc = by * 128 + no + ni * 8 + (lane & 3) * 2;
            #pragma unroll
            for (int h = 0; h < 2; ++h) {
                int r = bx * 128 + mo + mi * 16 + (lane >> 2) + h * 8;
                int n = r >> 8, p = r & 255;
                *reinterpret_cast<float2*>(&g_M[((size_t)(p * NN + n)) * BC + gc]) =
                    make_float2(acc[mi][ni][h * 2], acc[mi][ni][h * 2 + 1]);
            }
        }
}

// =============== pairwise L1 + exp (f32x2, higher occupancy) ===============
__global__ __launch_bounds__(256)
void mbd_pair(float* __restrict__ out) {
    __shared__ float Ms[NN * 128];       // 16 KB
    const int p  = blockIdx.x;
    const int bq = blockIdx.y;           // 16 b values (128 cols)
    const int t  = threadIdx.x;

    #pragma unroll
    for (int it = 0; it < 4; ++it) {
        int idx4 = t + 256 * it;         // 0..1023
        int n = idx4 >> 5, c4 = idx4 & 31;
        reinterpret_cast<float4*>(Ms)[idx4] =
            *reinterpret_cast<const float4*>(
                g_M + ((size_t)p * NN + n) * BC + bq * 128 + c4 * 4);
    }
    __syncthreads();

    const int b  = t & 15;
    const int ig = t >> 4;               // 0..15 -> 2 i rows each
    const unsigned long long NEG1 = 0xBF800000BF800000ULL;
    const unsigned long long AMSK = 0x7FFFFFFF7FFFFFFFULL;

    unsigned long long mi[2][4];
    #pragma unroll
    for (int ii = 0; ii < 2; ++ii) {
        const unsigned long long* row =
            reinterpret_cast<const unsigned long long*>(&Ms[(ig * 2 + ii) * 128 + b * 8]);
        mi[ii][0] = row[0]; mi[ii][1] = row[1];
        mi[ii][2] = row[2]; mi[ii][3] = row[3];
    }
    float o[2] = {0.f, 0.f};

    #pragma unroll 8
    for (int j = 0; j < NN; ++j) {
        const unsigned long long* row =
            reinterpret_cast<const unsigned long long*>(&Ms[j * 128 + b * 8]);
        unsigned long long jv0 = row[0], jv1 = row[1], jv2 = row[2], jv3 = row[3];
        #pragma unroll
        for (int ii = 0; ii < 2; ++ii) {
            unsigned long long d0 = fma2(jv0, NEG1, mi[ii][0]) & AMSK;
            unsigned long long d1 = fma2(jv1, NEG1, mi[ii][1]) & AMSK;
            unsigned long long d2 = fma2(jv2, NEG1, mi[ii][2]) & AMSK;
            unsigned long long d3 = fma2(jv3, NEG1, mi[ii][3]) & AMSK;
            unsigned long long s2 = add2(add2(d0, d1), add2(d2, d3));
            float s = __uint_as_float((uint32_t)s2) +
                      __uint_as_float((uint32_t)(s2 >> 32));
            o[ii] += __expf(-s);
        }
    }

    #pragma unroll
    for (int ii = 0; ii < 2; ++ii) {
        int n = ig * 2 + ii;
        out[((size_t)(n * PP + p)) * OUTC + FF + bq * 16 + b] = o[ii];
    }
}

// =============== launch ===============
extern "C" void kernel_launch(void* const* d_in, const int* in_sizes, int n_in,
                              void* d_out, int out_size) {
    const float* x;
    const float* T;
    if (in_sizes[0] == NN * PP * FF) {
        x = (const float*)d_in[0];
        T = (const float*)d_in[1];
    } else {
        x = (const float*)d_in[1];
        T = (const float*)d_in[0];
    }
    float* out = (float*)d_out;

    cudaFuncSetAttribute(mbd_gemm,
                         cudaFuncAttributeMaxDynamicSharedMemorySize, SMEM_GEMM);

    mbd_prep_t<<<dim3(8, 16), 256>>>(T);
    mbd_prep_x<<<2048, 256>>>(x, out);
    mbd_gemm<<<dim3(64, 4), 256, SMEM_GEMM>>>();
    mbd_pair<<<dim3(PP, 4), 256>>>(out);
}

// round 5
// speedup vs baseline: 2.3351x; 1.0495x over previous
#include <cuda_runtime.h>
#include <cuda_fp16.h>
#include <cstdint>

#define NN 32
#define PP 256
#define FF 256
#define BB 64
#define BC 512
#define OUTC 320
#define LOG2E 1.44269504088896340736f

// ---------------- device scratch ----------------
__device__ __half g_Th[BC * FF];          // [n=512][k=256] fp16, pre-scaled by log2(e)
__device__ __half g_Xh[NN * PP * FF];     // [r=8192][k=256]
__device__ __half g_Xl[NN * PP * FF];
__device__ float  g_M[PP * NN * BC];      // [p][n][512] (scaled by log2(e))

// ---------------- helpers ----------------
__device__ __forceinline__ uint32_t smem_u32(const void* p) {
    uint32_t a;
    asm("{ .reg .u64 t; cvta.to.shared.u64 t, %1; cvt.u32.u64 %0, t; }"
        : "=r"(a) : "l"(p));
    return a;
}

#define LDSM4(r, addr) \
    asm volatile("ldmatrix.sync.aligned.m8n8.x4.shared.b16 {%0,%1,%2,%3}, [%4];" \
        : "=r"((r)[0]), "=r"((r)[1]), "=r"((r)[2]), "=r"((r)[3]) : "r"(addr))

#define MMA_F16(c, a, b0, b1) \
    asm volatile("mma.sync.aligned.m16n8k16.row.col.f32.f16.f16.f32 " \
        "{%0,%1,%2,%3}, {%4,%5,%6,%7}, {%8,%9}, {%0,%1,%2,%3};" \
        : "+f"((c)[0]), "+f"((c)[1]), "+f"((c)[2]), "+f"((c)[3]) \
        : "r"((a)[0]), "r"((a)[1]), "r"((a)[2]), "r"((a)[3]), "r"(b0), "r"(b1))

__device__ __forceinline__ void cp16(uint32_t dst, const void* src) {
    asm volatile("cp.async.cg.shared.global [%0], [%1], 16;"
                 :: "r"(dst), "l"(src) : "memory");
}
#define CP_COMMIT() asm volatile("cp.async.commit_group;" ::: "memory")
#define CP_WAIT(n)  asm volatile("cp.async.wait_group %0;" :: "n"(n) : "memory")

__device__ __forceinline__ unsigned long long fma2(unsigned long long a,
                                                   unsigned long long b,
                                                   unsigned long long c) {
    unsigned long long d;
    asm("fma.rn.f32x2 %0, %1, %2, %3;" : "=l"(d) : "l"(a), "l"(b), "l"(c));
    return d;
}
__device__ __forceinline__ unsigned long long add2(unsigned long long a,
                                                   unsigned long long b) {
    unsigned long long d;
    asm("add.rn.f32x2 %0, %1, %2;" : "=l"(d) : "l"(a), "l"(b));
    return d;
}
__device__ __forceinline__ float ex2(float s) {
    float r;
    asm("ex2.approx.f32 %0, %1;" : "=f"(r) : "f"(s));
    return r;
}

// =============== fused prep: x split + passthrough, T transpose+scale ===============
__global__ __launch_bounds__(256)
void mbd_prep(const float* __restrict__ x, const float* __restrict__ T,
              float* __restrict__ out) {
    const int bid = blockIdx.x;
    if (bid < 2048) {
        // ---- x part ----
        const int idx4 = bid * 256 + threadIdx.x;   // float4 units
        const int r = idx4 >> 6;
        const int u = idx4 & 63;
        float4 v = *reinterpret_cast<const float4*>(x + (size_t)idx4 * 4);
        *reinterpret_cast<float4*>(out + (size_t)r * OUTC + u * 4) = v;
        __half h0 = __float2half(v.x), h1 = __float2half(v.y);
        __half h2 = __float2half(v.z), h3 = __float2half(v.w);
        __half2 hi0(h0, h1), hi1(h2, h3);
        __half2 lo0(__float2half(v.x - __half2float(h0)),
                    __float2half(v.y - __half2float(h1)));
        __half2 lo1(__float2half(v.z - __half2float(h2)),
                    __float2half(v.w - __half2float(h3)));
        *reinterpret_cast<uint2*>(g_Xh + (size_t)idx4 * 4) =
            make_uint2(*reinterpret_cast<uint32_t*>(&hi0),
                       *reinterpret_cast<uint32_t*>(&hi1));
        *reinterpret_cast<uint2*>(g_Xl + (size_t)idx4 * 4) =
            make_uint2(*reinterpret_cast<uint32_t*>(&lo0),
                       *reinterpret_cast<uint32_t*>(&lo1));
    } else {
        // ---- T part: transpose [f][n] -> [n][f], scale by log2(e), fp16 ----
        __shared__ float tile[32][33];
        const int b2 = bid - 2048;                  // 0..127
        const int f0 = (b2 & 7) * 32;
        const int n0 = (b2 >> 3) * 32;
        const int tx = threadIdx.x & 31;
        const int ty = threadIdx.x >> 5;
        #pragma unroll
        for (int r = 0; r < 4; ++r)
            tile[ty + 8 * r][tx] = T[(size_t)(f0 + ty + 8 * r) * BC + n0 + tx];
        __syncthreads();
        #pragma unroll
        for (int r = 0; r < 4; ++r) {
            int n = n0 + ty + 8 * r;
            int f = f0 + tx;
            g_Th[(size_t)n * FF + f] = __float2half(tile[tx][ty + 8 * r] * LOG2E);
        }
    }
}

// =============== GEMM: fp16 2-split HMMA, tile 128x128, double-buffered ===============
#define PAD 72
#define SA (128 * PAD)
#define STAGE_HALVES (3 * SA)
#define SMEM_GEMM (2 * STAGE_HALVES * 2) // 110592 bytes

__global__ __launch_bounds__(256, 2)
void mbd_gemm() {
    extern __shared__ __half sm[];
    const uint32_t smb = smem_u32(sm);
    const int t = threadIdx.x, w = t >> 5, lane = t & 31;
    const int bx = blockIdx.x;
    const int by = blockIdx.y;
    const int mo = (w >> 1) * 32;
    const int no = (w & 1) * 64;

    float acc[2][8][4];
    #pragma unroll
    for (int i = 0; i < 2; ++i)
        #pragma unroll
        for (int j = 0; j < 8; ++j)
            #pragma unroll
            for (int e = 0; e < 4; ++e) acc[i][j][e] = 0.f;

    auto stage = [&](int kc, int s) {
        const uint32_t base = smb + (uint32_t)(s * STAGE_HALVES) * 2;
        #pragma unroll
        for (int it = 0; it < 4; ++it) {
            int idx = t + 256 * it;
            int row = idx >> 3, u = idx & 7;
            uint32_t doff = (uint32_t)(row * PAD + u * 8) * 2;
            size_t so = (size_t)(bx * 128 + row) * FF + kc * 64 + u * 8;
            cp16(base + doff,              g_Xh + so);
            cp16(base + SA * 2 + doff,     g_Xl + so);
            size_t sb = (size_t)(by * 128 + row) * FF + kc * 64 + u * 8;
            cp16(base + 2 * SA * 2 + doff, g_Th + sb);
        }
        CP_COMMIT();
    };

    stage(0, 0);

    for (int kc = 0; kc < 4; ++kc) {
        if (kc < 3) stage(kc + 1, (kc + 1) & 1);
        if (kc < 3) { CP_WAIT(1); } else { CP_WAIT(0); }
        __syncthreads();

        const int s = kc & 1;
        const uint32_t a_base = smb + (uint32_t)(s * STAGE_HALVES) * 2;
        const uint32_t b_base = a_base + 2 * SA * 2;

        #pragma unroll
        for (int ks = 0; ks < 4; ++ks) {
            uint32_t afh[2][4], afl[2][4];
            #pragma unroll
            for (int mi = 0; mi < 2; ++mi) {
                uint32_t ad = a_base +
                    (uint32_t)(((mo + mi * 16 + (lane & 15)) * PAD) +
                               ks * 16 + (lane >> 4) * 8) * 2;
                LDSM4(afh[mi], ad);
                LDSM4(afl[mi], ad + SA * 2);
            }
            uint32_t bf[16];
            #pragma unroll
            for (int g = 0; g < 4; ++g) {
                uint32_t bd = b_base +
                    (uint32_t)(((no + g * 16 + ((lane >> 4) & 1) * 8 + (lane & 7)) * PAD) +
                               ks * 16 + ((lane >> 3) & 1) * 8) * 2;
                LDSM4(&bf[g * 4], bd);
            }
            #pragma unroll
            for (int mi = 0; mi < 2; ++mi)
                #pragma unroll
                for (int ni = 0; ni < 8; ++ni) {
                    MMA_F16(acc[mi][ni], afh[mi], bf[ni * 2], bf[ni * 2 + 1]);
                    MMA_F16(acc[mi][ni], afl[mi], bf[ni * 2], bf[ni * 2 + 1]);
                }
        }
        __syncthreads();
    }

    #pragma unroll
    for (int mi = 0; mi < 2; ++mi)
        #pragma unroll
        for (int ni = 0; ni < 8; ++ni) {
            int gc = by * 128 + no + ni * 8 + (lane & 3) * 2;
            #pragma unroll
            for (int h = 0; h < 2; ++h) {
                int r = bx * 128 + mo + mi * 16 + (lane >> 2) + h * 8;
                int n = r >> 8, p = r & 255;
                *reinterpret_cast<float2*>(&g_M[((size_t)(p * NN + n)) * BC + gc]) =
                    make_float2(acc[mi][ni][h * 2], acc[mi][ni][h * 2 + 1]);
            }
        }
}

// =============== pairwise L1 + exp2 (f32x2, 4 chains/thread) ===============
__global__ __launch_bounds__(128)
void mbd_pair(float* __restrict__ out) {
    __shared__ float Ms[NN * 128];       // 16 KB
    const int p  = blockIdx.x;
    const int bq = blockIdx.y;
    const int t  = threadIdx.x;

    #pragma unroll
    for (int it = 0; it < 8; ++it) {
        int idx4 = t + 128 * it;
        int n = idx4 >> 5, c4 = idx4 & 31;
        reinterpret_cast<float4*>(Ms)[idx4] =
            *reinterpret_cast<const float4*>(
                g_M + ((size_t)p * NN + n) * BC + bq * 128 + c4 * 4);
    }
    __syncthreads();

    const int b  = t & 15;
    const int ig = t >> 4;               // 0..7 -> 4 i rows each
    const unsigned long long NEG1 = 0xBF800000BF800000ULL;
    const unsigned long long AMSK = 0x7FFFFFFF7FFFFFFFULL;

    unsigned long long mi[4][4];
    #pragma unroll
    for (int ii = 0; ii < 4; ++ii) {
        const ulonglong2* row =
            reinterpret_cast<const ulonglong2*>(&Ms[(ig * 4 + ii) * 128 + b * 8]);
        ulonglong2 r0 = row[0], r1 = row[1];
        mi[ii][0] = r0.x; mi[ii][1] = r0.y;
        mi[ii][2] = r1.x; mi[ii][3] = r1.y;
    }
    float o[4] = {0.f, 0.f, 0.f, 0.f};

    #pragma unroll 8
    for (int j = 0; j < NN; ++j) {
        const ulonglong2* row =
            reinterpret_cast<const ulonglong2*>(&Ms[j * 128 + b * 8]);
        ulonglong2 r0 = row[0], r1 = row[1];
        unsigned long long jv0 = r0.x, jv1 = r0.y, jv2 = r1.x, jv3 = r1.y;
        #pragma unroll
        for (int ii = 0; ii < 4; ++ii) {
            unsigned long long d0 = fma2(jv0, NEG1, mi[ii][0]) & AMSK;
            unsigned long long d1 = fma2(jv1, NEG1, mi[ii][1]) & AMSK;
            unsigned long long d2 = fma2(jv2, NEG1, mi[ii][2]) & AMSK;
            unsigned long long d3 = fma2(jv3, NEG1, mi[ii][3]) & AMSK;
            unsigned long long s2 = add2(add2(d0, d1), add2(d2, d3));
            // s = -(lo + hi): FADD with negated sources (free), feeds EX2 directly
            float s = -__uint_as_float((uint32_t)s2) -
                       __uint_as_float((uint32_t)(s2 >> 32));
            o[ii] += ex2(s);
        }
    }

    #pragma unroll
    for (int ii = 0; ii < 4; ++ii) {
        int n = ig * 4 + ii;
        out[((size_t)(n * PP + p)) * OUTC + FF + bq * 16 + b] = o[ii];
    }
}

// =============== launch ===============
extern "C" void kernel_launch(void* const* d_in, const int* in_sizes, int n_in,
                              void* d_out, int out_size) {
    const float* x;
    const float* T;
    if (in_sizes[0] == NN * PP * FF) {
        x = (const float*)d_in[0];
        T = (const float*)d_in[1];
    } else {
        x = (const float*)d_in[1];
        T = (const float*)d_in[0];
    }
    float* out = (float*)d_out;

    cudaFuncSetAttribute(mbd_gemm,
                         cudaFuncAttributeMaxDynamicSharedMemorySize, SMEM_GEMM);

    mbd_prep<<<2048 + 128, 256>>>(x, T, out);
    mbd_gemm<<<dim3(64, 4), 256, SMEM_GEMM>>>();
    mbd_pair<<<dim3(PP, 4), 128>>>(out);
}

// round 6
// speedup vs baseline: 2.5655x; 1.0986x over previous
#include <cuda_runtime.h>
#include <cuda_fp16.h>
#include <cstdint>

#define NN 32
#define PP 256
#define FF 256
#define BB 64
#define BC 512
#define OUTC 320
#define LOG2E 1.44269504088896340736f

// ---------------- device scratch ----------------
// p-major row layout: row = p*NN + n
__device__ __half g_Th[BC * FF];          // [n=512][k=256] fp16, pre-scaled by log2(e)
__device__ __half g_Xh[NN * PP * FF];     // [row=8192][k=256]
__device__ __half g_Xl[NN * PP * FF];

// ---------------- helpers ----------------
__device__ __forceinline__ uint32_t smem_u32(const void* p) {
    uint32_t a;
    asm("{ .reg .u64 t; cvta.to.shared.u64 t, %1; cvt.u32.u64 %0, t; }"
        : "=r"(a) : "l"(p));
    return a;
}

#define LDSM4(r, addr) \
    asm volatile("ldmatrix.sync.aligned.m8n8.x4.shared.b16 {%0,%1,%2,%3}, [%4];" \
        : "=r"((r)[0]), "=r"((r)[1]), "=r"((r)[2]), "=r"((r)[3]) : "r"(addr))

#define MMA_F16(c, a, b0, b1) \
    asm volatile("mma.sync.aligned.m16n8k16.row.col.f32.f16.f16.f32 " \
        "{%0,%1,%2,%3}, {%4,%5,%6,%7}, {%8,%9}, {%0,%1,%2,%3};" \
        : "+f"((c)[0]), "+f"((c)[1]), "+f"((c)[2]), "+f"((c)[3]) \
        : "r"((a)[0]), "r"((a)[1]), "r"((a)[2]), "r"((a)[3]), "r"(b0), "r"(b1))

__device__ __forceinline__ void cp16(uint32_t dst, const void* src) {
    asm volatile("cp.async.cg.shared.global [%0], [%1], 16;"
                 :: "r"(dst), "l"(src) : "memory");
}
#define CP_COMMIT() asm volatile("cp.async.commit_group;" ::: "memory")
#define CP_WAIT(n)  asm volatile("cp.async.wait_group %0;" :: "n"(n) : "memory")

__device__ __forceinline__ unsigned long long fma2(unsigned long long a,
                                                   unsigned long long b,
                                                   unsigned long long c) {
    unsigned long long d;
    asm("fma.rn.f32x2 %0, %1, %2, %3;" : "=l"(d) : "l"(a), "l"(b), "l"(c));
    return d;
}
__device__ __forceinline__ unsigned long long add2(unsigned long long a,
                                                   unsigned long long b) {
    unsigned long long d;
    asm("add.rn.f32x2 %0, %1, %2;" : "=l"(d) : "l"(a), "l"(b));
    return d;
}
__device__ __forceinline__ float ex2(float s) {
    float r;
    asm("ex2.approx.f32 %0, %1;" : "=f"(r) : "f"(s));
    return r;
}

// =============== prep: x split (p-major rows) + passthrough; T transpose+scale ===============
__global__ __launch_bounds__(256)
void mbd_prep(const float* __restrict__ x, const float* __restrict__ T,
              float* __restrict__ out) {
    const int bid = blockIdx.x;
    const int t = threadIdx.x;
    if (bid < 512) {
        // ---- x part: 4 float4 per thread, front-batched (MLP=4) ----
        float4 v[4];
        int idx4[4];
        #pragma unroll
        for (int it = 0; it < 4; ++it) {
            idx4[it] = bid * 1024 + it * 256 + t;
            v[it] = *reinterpret_cast<const float4*>(x + (size_t)idx4[it] * 4);
        }
        #pragma unroll
        for (int it = 0; it < 4; ++it) {
            int r = idx4[it] >> 6;          // original row = n*PP + p
            int u = idx4[it] & 63;
            int n = r >> 8, p = r & 255;
            int rp = p * NN + n;            // p-major row
            *reinterpret_cast<float4*>(out + (size_t)r * OUTC + u * 4) = v[it];
            __half h0 = __float2half(v[it].x), h1 = __float2half(v[it].y);
            __half h2 = __float2half(v[it].z), h3 = __float2half(v[it].w);
            __half2 hi0(h0, h1), hi1(h2, h3);
            __half2 lo0(__float2half(v[it].x - __half2float(h0)),
                        __float2half(v[it].y - __half2float(h1)));
            __half2 lo1(__float2half(v[it].z - __half2float(h2)),
                        __float2half(v[it].w - __half2float(h3)));
            *reinterpret_cast<uint2*>(g_Xh + (size_t)rp * FF + u * 4) =
                make_uint2(*reinterpret_cast<uint32_t*>(&hi0),
                           *reinterpret_cast<uint32_t*>(&hi1));
            *reinterpret_cast<uint2*>(g_Xl + (size_t)rp * FF + u * 4) =
                make_uint2(*reinterpret_cast<uint32_t*>(&lo0),
                           *reinterpret_cast<uint32_t*>(&lo1));
        }
    } else {
        // ---- T part: transpose [f][n] -> [n][f], scale by log2(e), fp16 ----
        __shared__ float tile[32][33];
        const int b2 = bid - 512;           // 0..127
        const int f0 = (b2 & 7) * 32;
        const int n0 = (b2 >> 3) * 32;
        const int tx = t & 31;
        const int ty = t >> 5;
        #pragma unroll
        for (int r = 0; r < 4; ++r)
            tile[ty + 8 * r][tx] = T[(size_t)(f0 + ty + 8 * r) * BC + n0 + tx];
        __syncthreads();
        #pragma unroll
        for (int r = 0; r < 4; ++r) {
            int n = n0 + ty + 8 * r;
            int f = f0 + tx;
            g_Th[(size_t)n * FF + f] = __float2half(tile[tx][ty + 8 * r] * LOG2E);
        }
    }
}

// =============== fused GEMM (128x128x256, fp16 2-split) + pairwise ===============
#define PAD 72
#define SA (128 * PAD)
#define STAGE_HALVES (3 * SA)
#define SMEM_FUSED (2 * STAGE_HALVES * 2)   // 110592 bytes
#define MROW 132                            // padded M row (floats)

__global__ __launch_bounds__(256, 2)
void mbd_fused(float* __restrict__ out) {
    extern __shared__ __half sm[];
    const uint32_t smb = smem_u32(sm);
    float* Ms = reinterpret_cast<float*>(sm);   // reused after GEMM
    const int t = threadIdx.x, w = t >> 5, lane = t & 31;
    const int bx = blockIdx.x;                  // 64 pixel-groups (4 pixels)
    const int by = blockIdx.y;                  // 4 col tiles (16 b each)
    const int mo = (w >> 1) * 32;
    const int no = (w & 1) * 64;

    float acc[2][8][4];
    #pragma unroll
    for (int i = 0; i < 2; ++i)
        #pragma unroll
        for (int j = 0; j < 8; ++j)
            #pragma unroll
            for (int e = 0; e < 4; ++e) acc[i][j][e] = 0.f;

    auto stage = [&](int kc, int s) {
        const uint32_t base = smb + (uint32_t)(s * STAGE_HALVES) * 2;
        #pragma unroll
        for (int it = 0; it < 4; ++it) {
            int idx = t + 256 * it;
            int row = idx >> 3, u = idx & 7;
            uint32_t doff = (uint32_t)(row * PAD + u * 8) * 2;
            size_t so = (size_t)(bx * 128 + row) * FF + kc * 64 + u * 8;
            cp16(base + doff,              g_Xh + so);
            cp16(base + SA * 2 + doff,     g_Xl + so);
            size_t sb = (size_t)(by * 128 + row) * FF + kc * 64 + u * 8;
            cp16(base + 2 * SA * 2 + doff, g_Th + sb);
        }
        CP_COMMIT();
    };

    stage(0, 0);

    for (int kc = 0; kc < 4; ++kc) {
        if (kc < 3) stage(kc + 1, (kc + 1) & 1);
        if (kc < 3) { CP_WAIT(1); } else { CP_WAIT(0); }
        __syncthreads();

        const int s = kc & 1;
        const uint32_t a_base = smb + (uint32_t)(s * STAGE_HALVES) * 2;
        const uint32_t b_base = a_base + 2 * SA * 2;

        #pragma unroll
        for (int ks = 0; ks < 4; ++ks) {
            uint32_t afh[2][4], afl[2][4];
            #pragma unroll
            for (int mi = 0; mi < 2; ++mi) {
                uint32_t ad = a_base +
                    (uint32_t)(((mo + mi * 16 + (lane & 15)) * PAD) +
                               ks * 16 + (lane >> 4) * 8) * 2;
                LDSM4(afh[mi], ad);
                LDSM4(afl[mi], ad + SA * 2);
            }
            uint32_t bf[16];
            #pragma unroll
            for (int g = 0; g < 4; ++g) {
                uint32_t bd = b_base +
                    (uint32_t)(((no + g * 16 + ((lane >> 4) & 1) * 8 + (lane & 7)) * PAD) +
                               ks * 16 + ((lane >> 3) & 1) * 8) * 2;
                LDSM4(&bf[g * 4], bd);
            }
            #pragma unroll
            for (int mi = 0; mi < 2; ++mi)
                #pragma unroll
                for (int ni = 0; ni < 8; ++ni) {
                    MMA_F16(acc[mi][ni], afh[mi], bf[ni * 2], bf[ni * 2 + 1]);
                    MMA_F16(acc[mi][ni], afl[mi], bf[ni * 2], bf[ni * 2 + 1]);
                }
        }
        __syncthreads();
    }

    // ---- epilogue: accumulators -> smem M tile [128 rows][MROW] ----
    #pragma unroll
    for (int mi = 0; mi < 2; ++mi)
        #pragma unroll
        for (int ni = 0; ni < 8; ++ni) {
            int col = no + ni * 8 + (lane & 3) * 2;
            #pragma unroll
            for (int h = 0; h < 2; ++h) {
                int row = mo + mi * 16 + (lane >> 2) + h * 8;
                *reinterpret_cast<float2*>(&Ms[row * MROW + col]) =
                    make_float2(acc[mi][ni][h * 2], acc[mi][ni][h * 2 + 1]);
            }
        }
    __syncthreads();

    // ---- pairwise L1 + exp2 on the in-smem tile ----
    // rows: 4 pixels x 32 n ; cols: 16 b x 8 c
    const int pb  = t >> 2;        // 0..63
    const int p_l = pb >> 4;       // 0..3
    const int b_l = pb & 15;       // 0..15
    const int iq  = t & 3;         // 0..3
    const unsigned long long NEG1 = 0xBF800000BF800000ULL;
    const unsigned long long AMSK = 0x7FFFFFFF7FFFFFFFULL;

    const int p_g = bx * 4 + p_l;
    const int b_g = by * 16 + b_l;
    float* obase = out + (size_t)FF + b_g;

    #pragma unroll
    for (int pass = 0; pass < 2; ++pass) {
        const int i0 = pass * 16 + iq * 4;
        unsigned long long mi[4][4];
        #pragma unroll
        for (int ii = 0; ii < 4; ++ii) {
            const ulonglong2* row = reinterpret_cast<const ulonglong2*>(
                &Ms[(p_l * 32 + i0 + ii) * MROW + b_l * 8]);
            ulonglong2 r0 = row[0], r1 = row[1];
            mi[ii][0] = r0.x; mi[ii][1] = r0.y;
            mi[ii][2] = r1.x; mi[ii][3] = r1.y;
        }
        float o[4] = {0.f, 0.f, 0.f, 0.f};

        #pragma unroll 8
        for (int j = 0; j < NN; ++j) {
            const ulonglong2* row = reinterpret_cast<const ulonglong2*>(
                &Ms[(p_l * 32 + j) * MROW + b_l * 8]);
            ulonglong2 r0 = row[0], r1 = row[1];
            unsigned long long jv0 = r0.x, jv1 = r0.y, jv2 = r1.x, jv3 = r1.y;
            #pragma unroll
            for (int ii = 0; ii < 4; ++ii) {
                unsigned long long d0 = fma2(jv0, NEG1, mi[ii][0]) & AMSK;
                unsigned long long d1 = fma2(jv1, NEG1, mi[ii][1]) & AMSK;
                unsigned long long d2 = fma2(jv2, NEG1, mi[ii][2]) & AMSK;
                unsigned long long d3 = fma2(jv3, NEG1, mi[ii][3]) & AMSK;
                unsigned long long s2 = add2(add2(d0, d1), add2(d2, d3));
                float s = -__uint_as_float((uint32_t)s2) -
                           __uint_as_float((uint32_t)(s2 >> 32));
                o[ii] += ex2(s);
            }
        }

        #pragma unroll
        for (int ii = 0; ii < 4; ++ii) {
            int n = i0 + ii;
            obase[(size_t)(n * PP + p_g) * OUTC] = o[ii];
        }
    }
}

// =============== launch ===============
extern "C" void kernel_launch(void* const* d_in, const int* in_sizes, int n_in,
                              void* d_out, int out_size) {
    const float* x;
    const float* T;
    if (in_sizes[0] == NN * PP * FF) {
        x = (const float*)d_in[0];
        T = (const float*)d_in[1];
    } else {
        x = (const float*)d_in[1];
        T = (const float*)d_in[0];
    }
    float* out = (float*)d_out;

    cudaFuncSetAttribute(mbd_fused,
                         cudaFuncAttributeMaxDynamicSharedMemorySize, SMEM_FUSED);

    mbd_prep<<<512 + 128, 256>>>(x, T, out);
    mbd_fused<<<dim3(64, 4), 256, SMEM_FUSED>>>(out);
}

// round 7
// speedup vs baseline: 2.5830x; 1.0068x over previous
#include <cuda_runtime.h>
#include <cuda_fp16.h>
#include <cstdint>

#define NN 32
#define PP 256
#define FF 256
#define BB 64
#define BC 512
#define OUTC 320
#define LOG2E 1.44269504088896340736f

// ---------------- device scratch ----------------
// p-major row layout: row = p*NN + n
__device__ __half g_Th[BC * FF];          // [n=512][k=256] fp16, pre-scaled by log2(e)
__device__ __half g_Xh[NN * PP * FF];     // [row=8192][k=256]
__device__ __half g_Xl[NN * PP * FF];

// ---------------- helpers ----------------
__device__ __forceinline__ uint32_t smem_u32(const void* p) {
    uint32_t a;
    asm("{ .reg .u64 t; cvta.to.shared.u64 t, %1; cvt.u32.u64 %0, t; }"
        : "=r"(a) : "l"(p));
    return a;
}

#define LDSM4(r, addr) \
    asm volatile("ldmatrix.sync.aligned.m8n8.x4.shared.b16 {%0,%1,%2,%3}, [%4];" \
        : "=r"((r)[0]), "=r"((r)[1]), "=r"((r)[2]), "=r"((r)[3]) : "r"(addr))

#define MMA_F16(c, a, b0, b1) \
    asm volatile("mma.sync.aligned.m16n8k16.row.col.f32.f16.f16.f32 " \
        "{%0,%1,%2,%3}, {%4,%5,%6,%7}, {%8,%9}, {%0,%1,%2,%3};" \
        : "+f"((c)[0]), "+f"((c)[1]), "+f"((c)[2]), "+f"((c)[3]) \
        : "r"((a)[0]), "r"((a)[1]), "r"((a)[2]), "r"((a)[3]), "r"(b0), "r"(b1))

__device__ __forceinline__ void cp16(uint32_t dst, const void* src) {
    asm volatile("cp.async.cg.shared.global [%0], [%1], 16;"
                 :: "r"(dst), "l"(src) : "memory");
}
#define CP_COMMIT() asm volatile("cp.async.commit_group;" ::: "memory")
#define CP_WAIT(n)  asm volatile("cp.async.wait_group %0;" :: "n"(n) : "memory")

__device__ __forceinline__ unsigned long long fma2(unsigned long long a,
                                                   unsigned long long b,
                                                   unsigned long long c) {
    unsigned long long d;
    asm("fma.rn.f32x2 %0, %1, %2, %3;" : "=l"(d) : "l"(a), "l"(b), "l"(c));
    return d;
}
__device__ __forceinline__ unsigned long long add2(unsigned long long a,
                                                   unsigned long long b) {
    unsigned long long d;
    asm("add.rn.f32x2 %0, %1, %2;" : "=l"(d) : "l"(a), "l"(b));
    return d;
}
__device__ __forceinline__ float ex2(float s) {
    float r;
    asm("ex2.approx.f32 %0, %1;" : "=f"(r) : "f"(s));
    return r;
}

// =============== prep: x split (p-major rows) + passthrough; T transpose+scale ===============
__global__ __launch_bounds__(256)
void mbd_prep(const float* __restrict__ x, const float* __restrict__ T,
              float* __restrict__ out) {
    const int bid = blockIdx.x;
    const int t = threadIdx.x;
    if (bid < 512) {
        float4 v[4];
        int idx4[4];
        #pragma unroll
        for (int it = 0; it < 4; ++it) {
            idx4[it] = bid * 1024 + it * 256 + t;
            v[it] = *reinterpret_cast<const float4*>(x + (size_t)idx4[it] * 4);
        }
        #pragma unroll
        for (int it = 0; it < 4; ++it) {
            int r = idx4[it] >> 6;          // original row = n*PP + p
            int u = idx4[it] & 63;
            int n = r >> 8, p = r & 255;
            int rp = p * NN + n;            // p-major row
            *reinterpret_cast<float4*>(out + (size_t)r * OUTC + u * 4) = v[it];
            __half h0 = __float2half(v[it].x), h1 = __float2half(v[it].y);
            __half h2 = __float2half(v[it].z), h3 = __float2half(v[it].w);
            __half2 hi0(h0, h1), hi1(h2, h3);
            __half2 lo0(__float2half(v[it].x - __half2float(h0)),
                        __float2half(v[it].y - __half2float(h1)));
            __half2 lo1(__float2half(v[it].z - __half2float(h2)),
                        __float2half(v[it].w - __half2float(h3)));
            *reinterpret_cast<uint2*>(g_Xh + (size_t)rp * FF + u * 4) =
                make_uint2(*reinterpret_cast<uint32_t*>(&hi0),
                           *reinterpret_cast<uint32_t*>(&hi1));
            *reinterpret_cast<uint2*>(g_Xl + (size_t)rp * FF + u * 4) =
                make_uint2(*reinterpret_cast<uint32_t*>(&lo0),
                           *reinterpret_cast<uint32_t*>(&lo1));
        }
    } else {
        __shared__ float tile[32][33];
        const int b2 = bid - 512;
        const int f0 = (b2 & 7) * 32;
        const int n0 = (b2 >> 3) * 32;
        const int tx = t & 31;
        const int ty = t >> 5;
        #pragma unroll
        for (int r = 0; r < 4; ++r)
            tile[ty + 8 * r][tx] = T[(size_t)(f0 + ty + 8 * r) * BC + n0 + tx];
        __syncthreads();
        #pragma unroll
        for (int r = 0; r < 4; ++r) {
            int n = n0 + ty + 8 * r;
            int f = f0 + tx;
            g_Th[(size_t)n * FF + f] = __float2half(tile[tx][ty + 8 * r] * LOG2E);
        }
    }
}

// =============== fused GEMM (64x128x256, fp16 2-split) + pairwise ===============
#define PAD 72
#define SAH (64 * PAD)                      // A hi halves per stage
#define SBH (128 * PAD)                     // B halves per stage
#define STAGE_HALVES (2 * SAH + SBH)        // 18432 halves = 36864 B
#define SMEM_FUSED (2 * STAGE_HALVES * 2)   // 73728 bytes
#define MROW 132                            // padded M row (floats)

__global__ __launch_bounds__(256, 3)
void mbd_fused(float* __restrict__ out) {
    extern __shared__ __half sm[];
    const uint32_t smb = smem_u32(sm);
    float* Ms = reinterpret_cast<float*>(sm);   // reused after GEMM (stage-0 area)
    const int t = threadIdx.x, w = t >> 5, lane = t & 31;
    const int bx = blockIdx.x;                  // 128 pixel-pairs
    const int by = blockIdx.y;                  // 4 col tiles (16 b each)
    const int mo = (w >> 2) * 32;               // warp m offset (0,32)
    const int no = (w & 3) * 32;                // warp n offset (0,32,64,96)

    float acc[2][4][4];
    #pragma unroll
    for (int i = 0; i < 2; ++i)
        #pragma unroll
        for (int j = 0; j < 4; ++j)
            #pragma unroll
            for (int e = 0; e < 4; ++e) acc[i][j][e] = 0.f;

    auto stage = [&](int kc, int s) {
        const uint32_t base = smb + (uint32_t)(s * STAGE_HALVES) * 2;
        // A hi/lo: 64 rows x 64 halves = 512 cp16 each
        #pragma unroll
        for (int it = 0; it < 2; ++it) {
            int idx = t + 256 * it;
            int row = idx >> 3, u = idx & 7;
            uint32_t doff = (uint32_t)(row * PAD + u * 8) * 2;
            size_t so = (size_t)(bx * 64 + row) * FF + kc * 64 + u * 8;
            cp16(base + doff,           g_Xh + so);
            cp16(base + SAH * 2 + doff, g_Xl + so);
        }
        // B: 128 rows x 64 halves = 1024 cp16
        #pragma unroll
        for (int it = 0; it < 4; ++it) {
            int idx = t + 256 * it;
            int row = idx >> 3, u = idx & 7;
            uint32_t doff = (uint32_t)(row * PAD + u * 8) * 2;
            size_t sb = (size_t)(by * 128 + row) * FF + kc * 64 + u * 8;
            cp16(base + 2 * SAH * 2 + doff, g_Th + sb);
        }
        CP_COMMIT();
    };

    stage(0, 0);

    for (int kc = 0; kc < 4; ++kc) {
        if (kc < 3) stage(kc + 1, (kc + 1) & 1);
        if (kc < 3) { CP_WAIT(1); } else { CP_WAIT(0); }
        __syncthreads();

        const int s = kc & 1;
        const uint32_t a_base = smb + (uint32_t)(s * STAGE_HALVES) * 2;
        const uint32_t b_base = a_base + 2 * SAH * 2;

        #pragma unroll
        for (int ks = 0; ks < 4; ++ks) {
            uint32_t afh[2][4], afl[2][4];
            #pragma unroll
            for (int mi = 0; mi < 2; ++mi) {
                uint32_t ad = a_base +
                    (uint32_t)(((mo + mi * 16 + (lane & 15)) * PAD) +
                               ks * 16 + (lane >> 4) * 8) * 2;
                LDSM4(afh[mi], ad);
                LDSM4(afl[mi], ad + SAH * 2);
            }
            uint32_t bf[8];
            #pragma unroll
            for (int g = 0; g < 2; ++g) {
                uint32_t bd = b_base +
                    (uint32_t)(((no + g * 16 + ((lane >> 4) & 1) * 8 + (lane & 7)) * PAD) +
                               ks * 16 + ((lane >> 3) & 1) * 8) * 2;
                LDSM4(&bf[g * 4], bd);
            }
            #pragma unroll
            for (int mi = 0; mi < 2; ++mi)
                #pragma unroll
                for (int ni = 0; ni < 4; ++ni) {
                    MMA_F16(acc[mi][ni], afh[mi], bf[ni * 2], bf[ni * 2 + 1]);
                    MMA_F16(acc[mi][ni], afl[mi], bf[ni * 2], bf[ni * 2 + 1]);
                }
        }
        __syncthreads();
    }

    // ---- epilogue: accumulators -> smem M tile [64 rows][MROW] ----
    #pragma unroll
    for (int mi = 0; mi < 2; ++mi)
        #pragma unroll
        for (int ni = 0; ni < 4; ++ni) {
            int col = no + ni * 8 + (lane & 3) * 2;
            #pragma unroll
            for (int h = 0; h < 2; ++h) {
                int row = mo + mi * 16 + (lane >> 2) + h * 8;
                *reinterpret_cast<float2*>(&Ms[row * MROW + col]) =
                    make_float2(acc[mi][ni][h * 2], acc[mi][ni][h * 2 + 1]);
            }
        }
    __syncthreads();

    // ---- pairwise L1 + exp2 on the in-smem tile ----
    // rows: 2 pixels x 32 n ; cols: 16 b x 8 c
    const int p_l = t >> 7;            // 0..1
    const int rem = t & 127;
    const int b_l = rem >> 3;          // 0..15
    const int io  = rem & 7;           // 0..7 (4 i rows each)
    const unsigned long long NEG1 = 0xBF800000BF800000ULL;
    const unsigned long long AMSK = 0x7FFFFFFF7FFFFFFFULL;

    const int p_g = bx * 2 + p_l;
    const int b_g = by * 16 + b_l;

    unsigned long long mi[4][4];
    #pragma unroll
    for (int ii = 0; ii < 4; ++ii) {
        const ulonglong2* row = reinterpret_cast<const ulonglong2*>(
            &Ms[(p_l * 32 + io * 4 + ii) * MROW + b_l * 8]);
        ulonglong2 r0 = row[0], r1 = row[1];
        mi[ii][0] = r0.x; mi[ii][1] = r0.y;
        mi[ii][2] = r1.x; mi[ii][3] = r1.y;
    }
    float o[4] = {0.f, 0.f, 0.f, 0.f};

    #pragma unroll 8
    for (int j = 0; j < NN; ++j) {
        const ulonglong2* row = reinterpret_cast<const ulonglong2*>(
            &Ms[(p_l * 32 + j) * MROW + b_l * 8]);
        ulonglong2 r0 = row[0], r1 = row[1];
        unsigned long long jv0 = r0.x, jv1 = r0.y, jv2 = r1.x, jv3 = r1.y;
        #pragma unroll
        for (int ii = 0; ii < 4; ++ii) {
            unsigned long long d0 = fma2(jv0, NEG1, mi[ii][0]) & AMSK;
            unsigned long long d1 = fma2(jv1, NEG1, mi[ii][1]) & AMSK;
            unsigned long long d2 = fma2(jv2, NEG1, mi[ii][2]) & AMSK;
            unsigned long long d3 = fma2(jv3, NEG1, mi[ii][3]) & AMSK;
            unsigned long long s2 = add2(add2(d0, d1), add2(d2, d3));
            float s = -__uint_as_float((uint32_t)s2) -
                       __uint_as_float((uint32_t)(s2 >> 32));
            o[ii] += ex2(s);
        }
    }

    #pragma unroll
    for (int ii = 0; ii < 4; ++ii) {
        int n = io * 4 + ii;
        out[(size_t)(n * PP + p_g) * OUTC + FF + b_g] = o[ii];
    }
}

// =============== launch ===============
extern "C" void kernel_launch(void* const* d_in, const int* in_sizes, int n_in,
                              void* d_out, int out_size) {
    const float* x;
    const float* T;
    if (in_sizes[0] == NN * PP * FF) {
        x = (const float*)d_in[0];
        T = (const float*)d_in[1];
    } else {
        x = (const float*)d_in[1];
        T = (const float*)d_in[0];
    }
    float* out = (float*)d_out;

    cudaFuncSetAttribute(mbd_fused,
                         cudaFuncAttributeMaxDynamicSharedMemorySize, SMEM_FUSED);

    mbd_prep<<<512 + 128, 256>>>(x, T, out);
    mbd_fused<<<dim3(128, 4), 256, SMEM_FUSED>>>(out);
}

// round 8
// speedup vs baseline: 2.7679x; 1.0716x over previous
#include <cuda_runtime.h>
#include <cuda_fp16.h>
#include <cstdint>

#define NN 32
#define PP 256
#define FF 256
#define BB 64
#define BC 512
#define OUTC 320
#define LOG2E 1.44269504088896340736f

// ---------------- device scratch ----------------
// p-major row layout: row = p*NN + n
__device__ __half g_Th[BC * FF];          // [n=512][k=256] fp16, pre-scaled by log2(e)
__device__ __half g_Xh[NN * PP * FF];     // [row=8192][k=256]
__device__ __half g_Xl[NN * PP * FF];

// ---------------- helpers ----------------
__device__ __forceinline__ uint32_t smem_u32(const void* p) {
    uint32_t a;
    asm("{ .reg .u64 t; cvta.to.shared.u64 t, %1; cvt.u32.u64 %0, t; }"
        : "=r"(a) : "l"(p));
    return a;
}

#define LDSM4(r, addr) \
    asm volatile("ldmatrix.sync.aligned.m8n8.x4.shared.b16 {%0,%1,%2,%3}, [%4];" \
        : "=r"((r)[0]), "=r"((r)[1]), "=r"((r)[2]), "=r"((r)[3]) : "r"(addr))

#define MMA_F16(c, a, b0, b1) \
    asm volatile("mma.sync.aligned.m16n8k16.row.col.f32.f16.f16.f32 " \
        "{%0,%1,%2,%3}, {%4,%5,%6,%7}, {%8,%9}, {%0,%1,%2,%3};" \
        : "+f"((c)[0]), "+f"((c)[1]), "+f"((c)[2]), "+f"((c)[3]) \
        : "r"((a)[0]), "r"((a)[1]), "r"((a)[2]), "r"((a)[3]), "r"(b0), "r"(b1))

__device__ __forceinline__ void cp16(uint32_t dst, const void* src) {
    asm volatile("cp.async.cg.shared.global [%0], [%1], 16;"
                 :: "r"(dst), "l"(src) : "memory");
}
#define CP_COMMIT() asm volatile("cp.async.commit_group;" ::: "memory")
#define CP_WAIT(n)  asm volatile("cp.async.wait_group %0;" :: "n"(n) : "memory")

__device__ __forceinline__ unsigned long long fma2(unsigned long long a,
                                                   unsigned long long b,
                                                   unsigned long long c) {
    unsigned long long d;
    asm("fma.rn.f32x2 %0, %1, %2, %3;" : "=l"(d) : "l"(a), "l"(b), "l"(c));
    return d;
}
__device__ __forceinline__ unsigned long long add2(unsigned long long a,
                                                   unsigned long long b) {
    unsigned long long d;
    asm("add.rn.f32x2 %0, %1, %2;" : "=l"(d) : "l"(a), "l"(b));
    return d;
}
__device__ __forceinline__ float ex2(float s) {
    float r;
    asm("ex2.approx.f32 %0, %1;" : "=f"(r) : "f"(s));
    return r;
}

// =============== prep: x split (p-major rows) + passthrough; T transpose+scale ===============
__global__ __launch_bounds__(256)
void mbd_prep(const float* __restrict__ x, const float* __restrict__ T,
              float* __restrict__ out) {
    const int bid = blockIdx.x;
    const int t = threadIdx.x;
    if (bid < 512) {
        float4 v[4];
        int idx4[4];
        #pragma unroll
        for (int it = 0; it < 4; ++it) {
            idx4[it] = bid * 1024 + it * 256 + t;
            v[it] = *reinterpret_cast<const float4*>(x + (size_t)idx4[it] * 4);
        }
        #pragma unroll
        for (int it = 0; it < 4; ++it) {
            int r = idx4[it] >> 6;          // original row = n*PP + p
            int u = idx4[it] & 63;
            int n = r >> 8, p = r & 255;
            int rp = p * NN + n;            // p-major row
            *reinterpret_cast<float4*>(out + (size_t)r * OUTC + u * 4) = v[it];
            __half h0 = __float2half(v[it].x), h1 = __float2half(v[it].y);
            __half h2 = __float2half(v[it].z), h3 = __float2half(v[it].w);
            __half2 hi0(h0, h1), hi1(h2, h3);
            __half2 lo0(__float2half(v[it].x - __half2float(h0)),
                        __float2half(v[it].y - __half2float(h1)));
            __half2 lo1(__float2half(v[it].z - __half2float(h2)),
                        __float2half(v[it].w - __half2float(h3)));
            *reinterpret_cast<uint2*>(g_Xh + (size_t)rp * FF + u * 4) =
                make_uint2(*reinterpret_cast<uint32_t*>(&hi0),
                           *reinterpret_cast<uint32_t*>(&hi1));
            *reinterpret_cast<uint2*>(g_Xl + (size_t)rp * FF + u * 4) =
                make_uint2(*reinterpret_cast<uint32_t*>(&lo0),
                           *reinterpret_cast<uint32_t*>(&lo1));
        }
    } else {
        __shared__ float tile[32][33];
        const int b2 = bid - 512;
        const int f0 = (b2 & 7) * 32;
        const int n0 = (b2 >> 3) * 32;
        const int tx = t & 31;
        const int ty = t >> 5;
        #pragma unroll
        for (int r = 0; r < 4; ++r)
            tile[ty + 8 * r][tx] = T[(size_t)(f0 + ty + 8 * r) * BC + n0 + tx];
        __syncthreads();
        #pragma unroll
        for (int r = 0; r < 4; ++r) {
            int n = n0 + ty + 8 * r;
            int f = f0 + tx;
            g_Th[(size_t)n * FF + f] = __float2half(tile[tx][ty + 8 * r] * LOG2E);
        }
    }
}

// =============== fused GEMM (64x128x256, fp16 2-split) + symmetric pairwise ===============
#define PAD 72
#define SAH (64 * PAD)                      // A hi halves per stage
#define SBH (128 * PAD)                     // B halves per stage
#define STAGE_HALVES (2 * SAH + SBH)        // 18432 halves = 36864 B
#define SMEM_FUSED (2 * STAGE_HALVES * 2)   // 73728 bytes
#define MROW 132                            // padded M row (floats)
#define OPART_OFF 33792                     // bytes: after Ms (64*132*4)

__global__ __launch_bounds__(256, 3)
void mbd_fused(float* __restrict__ out) {
    extern __shared__ __half sm[];
    const uint32_t smb = smem_u32(sm);
    float* Ms = reinterpret_cast<float*>(sm);   // reused after GEMM
    float* o_part = reinterpret_cast<float*>(
        reinterpret_cast<char*>(sm) + OPART_OFF);  // [32 grp][4 src][32 i] = 16KB
    const int t = threadIdx.x, w = t >> 5, lane = t & 31;
    const int bx = blockIdx.x;                  // 128 pixel-pairs
    const int by = blockIdx.y;                  // 4 col tiles (16 b each)
    const int mo = (w >> 2) * 32;
    const int no = (w & 3) * 32;

    float acc[2][4][4];
    #pragma unroll
    for (int i = 0; i < 2; ++i)
        #pragma unroll
        for (int j = 0; j < 4; ++j)
            #pragma unroll
            for (int e = 0; e < 4; ++e) acc[i][j][e] = 0.f;

    auto stage = [&](int kc, int s) {
        const uint32_t base = smb + (uint32_t)(s * STAGE_HALVES) * 2;
        #pragma unroll
        for (int it = 0; it < 2; ++it) {
            int idx = t + 256 * it;
            int row = idx >> 3, u = idx & 7;
            uint32_t doff = (uint32_t)(row * PAD + u * 8) * 2;
            size_t so = (size_t)(bx * 64 + row) * FF + kc * 64 + u * 8;
            cp16(base + doff,           g_Xh + so);
            cp16(base + SAH * 2 + doff, g_Xl + so);
        }
        #pragma unroll
        for (int it = 0; it < 4; ++it) {
            int idx = t + 256 * it;
            int row = idx >> 3, u = idx & 7;
            uint32_t doff = (uint32_t)(row * PAD + u * 8) * 2;
            size_t sb = (size_t)(by * 128 + row) * FF + kc * 64 + u * 8;
            cp16(base + 2 * SAH * 2 + doff, g_Th + sb);
        }
        CP_COMMIT();
    };

    stage(0, 0);

    for (int kc = 0; kc < 4; ++kc) {
        if (kc < 3) stage(kc + 1, (kc + 1) & 1);
        if (kc < 3) { CP_WAIT(1); } else { CP_WAIT(0); }
        __syncthreads();

        const int s = kc & 1;
        const uint32_t a_base = smb + (uint32_t)(s * STAGE_HALVES) * 2;
        const uint32_t b_base = a_base + 2 * SAH * 2;

        #pragma unroll
        for (int ks = 0; ks < 4; ++ks) {
            uint32_t afh[2][4], afl[2][4];
            #pragma unroll
            for (int mi = 0; mi < 2; ++mi) {
                uint32_t ad = a_base +
                    (uint32_t)(((mo + mi * 16 + (lane & 15)) * PAD) +
                               ks * 16 + (lane >> 4) * 8) * 2;
                LDSM4(afh[mi], ad);
                LDSM4(afl[mi], ad + SAH * 2);
            }
            uint32_t bf[8];
            #pragma unroll
            for (int g = 0; g < 2; ++g) {
                uint32_t bd = b_base +
                    (uint32_t)(((no + g * 16 + ((lane >> 4) & 1) * 8 + (lane & 7)) * PAD) +
                               ks * 16 + ((lane >> 3) & 1) * 8) * 2;
                LDSM4(&bf[g * 4], bd);
            }
            #pragma unroll
            for (int mi = 0; mi < 2; ++mi)
                #pragma unroll
                for (int ni = 0; ni < 4; ++ni) {
                    MMA_F16(acc[mi][ni], afh[mi], bf[ni * 2], bf[ni * 2 + 1]);
                    MMA_F16(acc[mi][ni], afl[mi], bf[ni * 2], bf[ni * 2 + 1]);
                }
        }
        __syncthreads();
    }

    // ---- epilogue: accumulators -> smem M tile [64 rows][MROW] ----
    #pragma unroll
    for (int mi = 0; mi < 2; ++mi)
        #pragma unroll
        for (int ni = 0; ni < 4; ++ni) {
            int col = no + ni * 8 + (lane & 3) * 2;
            #pragma unroll
            for (int h = 0; h < 2; ++h) {
                int row = mo + mi * 16 + (lane >> 2) + h * 8;
                *reinterpret_cast<float2*>(&Ms[row * MROW + col]) =
                    make_float2(acc[mi][ni][h * 2], acc[mi][ni][h * 2 + 1]);
            }
        }
    __syncthreads();

    // ---- symmetric pairwise L1 + exp2 ----
    // thread layout: p_l (2) x b_l (16) x io (8). Thread io owns rows [4io, 4io+4).
    // Block-pairs: (io, (io+s)%8), s=0..4; s=4 only for io<4.
    const int p_l = t >> 7;
    const int rem = t & 127;
    const int b_l = rem >> 3;
    const int io  = rem & 7;
    const int grp = p_l * 16 + b_l;           // 0..31
    const unsigned long long NEG1 = 0xBF800000BF800000ULL;
    const unsigned long long AMSK = 0x7FFFFFFF7FFFFFFFULL;

    const int p_g = bx * 2 + p_l;
    const int b_g = by * 16 + b_l;

    unsigned long long mi[4][4];
    #pragma unroll
    for (int ii = 0; ii < 4; ++ii) {
        const ulonglong2* row = reinterpret_cast<const ulonglong2*>(
            &Ms[(p_l * 32 + io * 4 + ii) * MROW + b_l * 8]);
        ulonglong2 r0 = row[0], r1 = row[1];
        mi[ii][0] = r0.x; mi[ii][1] = r0.y;
        mi[ii][2] = r1.x; mi[ii][3] = r1.y;
    }
    float rowacc[4] = {0.f, 0.f, 0.f, 0.f};

    #pragma unroll
    for (int s = 0; s <= 4; ++s) {
        if (s == 4 && io >= 4) break;
        const int bblk = (io + s) & 7;
        float cacc[4] = {0.f, 0.f, 0.f, 0.f};
        #pragma unroll
        for (int jj = 0; jj < 4; ++jj) {
            const ulonglong2* row = reinterpret_cast<const ulonglong2*>(
                &Ms[(p_l * 32 + bblk * 4 + jj) * MROW + b_l * 8]);
            ulonglong2 r0 = row[0], r1 = row[1];
            unsigned long long jv0 = r0.x, jv1 = r0.y, jv2 = r1.x, jv3 = r1.y;
            #pragma unroll
            for (int ii = 0; ii < 4; ++ii) {
                unsigned long long d0 = fma2(jv0, NEG1, mi[ii][0]) & AMSK;
                unsigned long long d1 = fma2(jv1, NEG1, mi[ii][1]) & AMSK;
                unsigned long long d2 = fma2(jv2, NEG1, mi[ii][2]) & AMSK;
                unsigned long long d3 = fma2(jv3, NEG1, mi[ii][3]) & AMSK;
                unsigned long long s2 = add2(add2(d0, d1), add2(d2, d3));
                float sv = -__uint_as_float((uint32_t)s2) -
                            __uint_as_float((uint32_t)(s2 >> 32));
                float e = ex2(sv);
                rowacc[ii] += e;
                if (s) cacc[jj] += e;
            }
        }
        if (s) {
            // scatter col sums: target rows bblk*4+jj, source slot s-1 (unique writer)
            float* dst = &o_part[(grp * 4 + (s - 1)) * 32 + bblk * 4];
            dst[0] = cacc[0]; dst[1] = cacc[1];
            dst[2] = cacc[2]; dst[3] = cacc[3];
        }
    }
    __syncthreads();

    // reduce: own rowacc + 3 (or 4) column-contribution slots
    #pragma unroll
    for (int ii = 0; ii < 4; ++ii) {
        int i = io * 4 + ii;
        float v = rowacc[ii]
                + o_part[(grp * 4 + 0) * 32 + i]
                + o_part[(grp * 4 + 1) * 32 + i]
                + o_part[(grp * 4 + 2) * 32 + i];
        if (io >= 4) v += o_part[(grp * 4 + 3) * 32 + i];
        out[(size_t)(i * PP + p_g) * OUTC + FF + b_g] = v;
    }
}

// =============== launch ===============
extern "C" void kernel_launch(void* const* d_in, const int* in_sizes, int n_in,
                              void* d_out, int out_size) {
    const float* x;
    const float* T;
    if (in_sizes[0] == NN * PP * FF) {
        x = (const float*)d_in[0];
        T = (const float*)d_in[1];
    } else {
        x = (const float*)d_in[1];
        T = (const float*)d_in[0];
    }
    float* out = (float*)d_out;

    cudaFuncSetAttribute(mbd_fused,
                         cudaFuncAttributeMaxDynamicSharedMemorySize, SMEM_FUSED);

    mbd_prep<<<512 + 128, 256>>>(x, T, out);
    mbd_fused<<<dim3(128, 4), 256, SMEM_FUSED>>>(out);
}